// round 4
// baseline (speedup 1.0000x reference)
#include <cuda_runtime.h>

#define NGg 8192
#define NCc 4096
#define FGk 512
#define FCk 256
#define DD 64
#define ALPHA 0.2f
#define NEGV -1.0e30f
#define PW 68   // padded psh row stride (mult of 4, breaks bank conflict)

// ---------------- scratch (static device allocations) ----------------
__device__ float g_gene_h[NGg * DD];
__device__ float g_cell_h[NCc * DD];
__device__ float g_gg[NGg * DD];
__device__ float g_gc[NGg * DD];
__device__ float g_cc[NCc * DD];
__device__ float g_cg[NCc * DD];
__device__ float g_s_gg1[NGg], g_s_gg2[NGg], g_s_gc1[NGg], g_s_cg2[NGg], g_gam_g[NGg];
__device__ float g_s_cc1[NCc], g_s_cc2[NCc], g_s_gc2[NCc], g_s_cg1[NCc], g_gam_c[NCc];

__device__ __forceinline__ float leaky(float x) { return x >= 0.f ? x : ALPHA * x; }

// ---------------- feature GEMM: H[M,64] = X[M,K] @ W[K,64] ----------------
// block = 16 rows x 64 cols, 256 threads (4 row-groups x 64 d)
__global__ void gemm64_kernel(const float* __restrict__ X, const float* __restrict__ W,
                              int K, int which) {
    __shared__ float xs[16 * FGk];
    float* H = which ? g_cell_h : g_gene_h;
    const int m0 = blockIdx.x * 16;
    const int tid = threadIdx.x;

    const int nf4 = 16 * K / 4;
    const float4* src = (const float4*)(X + (size_t)m0 * K);
    float4* dst = (float4*)xs;
    for (int i = tid; i < nf4; i += 256) dst[i] = src[i];
    __syncthreads();

    const int d = tid & 63;
    const int rg = tid >> 6;
    float a0 = 0.f, a1 = 0.f, a2 = 0.f, a3 = 0.f;
    const float* xr = xs + (rg * 4) * K;
#pragma unroll 4
    for (int k = 0; k < K; k++) {
        float w = W[k * 64 + d];
        a0 += xr[k] * w;
        a1 += xr[K + k] * w;
        a2 += xr[2 * K + k] * w;
        a3 += xr[3 * K + k] * w;
    }
    const int row = m0 + rg * 4;
    H[(row + 0) * 64 + d] = a0;
    H[(row + 1) * 64 + d] = a1;
    H[(row + 2) * 64 + d] = a2;
    H[(row + 3) * 64 + d] = a3;
}

// ---------------- score vectors + gates ----------------
__device__ __forceinline__ float warp_dot(float v0, float v1, const float* __restrict__ vec, int lane) {
    float t = v0 * vec[lane] + v1 * vec[lane + 32];
#pragma unroll
    for (int off = 16; off; off >>= 1) t += __shfl_xor_sync(0xFFFFFFFFu, t, off);
    return t;
}

__global__ void svec_kernel(const float* __restrict__ a_gg, const float* __restrict__ a_gc,
                            const float* __restrict__ a_cc, const float* __restrict__ a_cg,
                            const float* __restrict__ Wg, const float* __restrict__ bg,
                            const float* __restrict__ Wc, const float* __restrict__ bc) {
    const int w = blockIdx.x * 8 + (threadIdx.x >> 5);
    const int lane = threadIdx.x & 31;
    if (w < NGg) {
        const float* h = g_gene_h + (size_t)w * 64;
        float v0 = h[lane], v1 = h[lane + 32];
        float d1 = warp_dot(v0, v1, a_gg, lane);
        float d2 = warp_dot(v0, v1, a_gg + 64, lane);
        float d3 = warp_dot(v0, v1, a_gc, lane);
        float d4 = warp_dot(v0, v1, a_cg + 64, lane);
        float dg = warp_dot(v0, v1, Wg, lane);
        if (lane == 0) {
            g_s_gg1[w] = d1; g_s_gg2[w] = d2; g_s_gc1[w] = d3; g_s_cg2[w] = d4;
            g_gam_g[w] = 1.0f / (1.0f + expf(-(dg + bg[0])));
        }
    } else if (w < NGg + NCc) {
        const int r = w - NGg;
        const float* h = g_cell_h + (size_t)r * 64;
        float v0 = h[lane], v1 = h[lane + 32];
        float d1 = warp_dot(v0, v1, a_cc, lane);
        float d2 = warp_dot(v0, v1, a_cc + 64, lane);
        float d3 = warp_dot(v0, v1, a_gc + 64, lane);
        float d4 = warp_dot(v0, v1, a_cg, lane);
        float dg = warp_dot(v0, v1, Wc, lane);
        if (lane == 0) {
            g_s_cc1[r] = d1; g_s_cc2[r] = d2; g_s_gc2[r] = d3; g_s_cg1[r] = d4;
            g_gam_c[r] = 1.0f / (1.0f + expf(-(dg + bc[0])));
        }
    }
}

// ---------------- fused relation kernel (4 relations, online softmax, 64x64 tiles) ----------------
// blocks: [0,128) gg | [128,256) gc | [256,320) cc | [320,384) cg (transposed adj)
__global__ __launch_bounds__(256) void rel_kernel(const int* __restrict__ gadj,
                                                  const int* __restrict__ cadj,
                                                  const int* __restrict__ gca) {
    __shared__ float s1sh[64];
    __shared__ float s2sh[64];
    __shared__ float hsh[64 * 64];
    __shared__ float psh[64 * PW];
    __shared__ unsigned char adjsh[64 * 64];

    const int b = blockIdx.x;
    const float *s1g, *s2g, *hd;
    float* outp;
    const int* adj;
    int Nd, i0, rowStride;
    bool trans = false;
    if (b < 128) {
        i0 = b * 64; Nd = NGg; s1g = g_s_gg1; s2g = g_s_gg2; hd = g_gene_h;
        adj = gadj; rowStride = NGg; outp = g_gg;
    } else if (b < 256) {
        i0 = (b - 128) * 64; Nd = NCc; s1g = g_s_gc1; s2g = g_s_gc2; hd = g_cell_h;
        adj = gca; rowStride = NCc; outp = g_gc;
    } else if (b < 320) {
        i0 = (b - 256) * 64; Nd = NCc; s1g = g_s_cc1; s2g = g_s_cc2; hd = g_cell_h;
        adj = cadj; rowStride = NCc; outp = g_cc;
    } else {
        i0 = (b - 320) * 64; Nd = NGg; s1g = g_s_cg1; s2g = g_s_cg2; hd = g_gene_h;
        adj = gca; rowStride = NCc; trans = true; outp = g_cg;
    }

    const int tid = threadIdx.x;
    const int tx = tid & 15;   // dim group / j group
    const int ty = tid >> 4;   // row group
    if (tid < 64) s1sh[tid] = s1g[i0 + tid];

    float m[4], l[4], acc[4][4];
#pragma unroll
    for (int rr = 0; rr < 4; rr++) {
        m[rr] = NEGV; l[rr] = 0.f;
#pragma unroll
        for (int dd = 0; dd < 4; dd++) acc[rr][dd] = 0.f;
    }

    const int nt = Nd / 64;
    for (int jt = 0; jt < nt; jt++) {
        const int j0 = jt * 64;
        if (tid < 64) s2sh[tid] = s2g[j0 + tid];
        // h tile (64x64 fp32)
#pragma unroll
        for (int ph = 0; ph < 4; ph++) {
            int idx = tid + ph * 256;              // float4 index 0..1023
            int jj = idx >> 4;
            int d4 = (idx & 15) << 2;
            *(float4*)&hsh[jj * 64 + d4] = *(const float4*)&hd[(size_t)(j0 + jj) * 64 + d4];
        }
        // adjacency tile -> bytes
        if (!trans) {
#pragma unroll
            for (int q = 0; q < 4; q++) {
                int i4 = tid + q * 256;            // int4 index
                int r = i4 >> 4;
                int c0 = (i4 & 15) << 2;
                int4 v = *(const int4*)&adj[(size_t)(i0 + r) * rowStride + j0 + c0];
                adjsh[r * 64 + c0 + 0] = (unsigned char)(v.x > 0);
                adjsh[r * 64 + c0 + 1] = (unsigned char)(v.y > 0);
                adjsh[r * 64 + c0 + 2] = (unsigned char)(v.z > 0);
                adjsh[r * 64 + c0 + 3] = (unsigned char)(v.w > 0);
            }
        } else {
#pragma unroll
            for (int q = 0; q < 4; q++) {
                int i4 = tid + q * 256;
                int c = i4 >> 4;
                int r0 = (i4 & 15) << 2;
                int4 v = *(const int4*)&adj[(size_t)(j0 + c) * rowStride + i0 + r0];
                adjsh[(r0 + 0) * 64 + c] = (unsigned char)(v.x > 0);
                adjsh[(r0 + 1) * 64 + c] = (unsigned char)(v.y > 0);
                adjsh[(r0 + 2) * 64 + c] = (unsigned char)(v.z > 0);
                adjsh[(r0 + 3) * 64 + c] = (unsigned char)(v.w > 0);
            }
        }
        __syncthreads();

        // ---- score / online softmax ----
#pragma unroll
        for (int rr = 0; rr < 4; rr++) {
            const int r = ty * 4 + rr;
            const float s1v = s1sh[r];
            uchar4 av = *(uchar4*)&adjsh[r * 64 + tx * 4];
            float t, e0, e1, e2, e3;
            t = s1v + s2sh[tx * 4 + 0]; e0 = av.x ? leaky(t) : NEGV;
            t = s1v + s2sh[tx * 4 + 1]; e1 = av.y ? leaky(t) : NEGV;
            t = s1v + s2sh[tx * 4 + 2]; e2 = av.z ? leaky(t) : NEGV;
            t = s1v + s2sh[tx * 4 + 3]; e3 = av.w ? leaky(t) : NEGV;
            float mr = fmaxf(fmaxf(e0, e1), fmaxf(e2, e3));
#pragma unroll
            for (int off = 1; off < 16; off <<= 1)
                mr = fmaxf(mr, __shfl_xor_sync(0xFFFFFFFFu, mr, off));
            const float mn = fmaxf(m[rr], mr);
            const float sc = __expf(m[rr] - mn);
            float p0 = (e0 <= -1e29f) ? 0.f : __expf(e0 - mn);
            float p1 = (e1 <= -1e29f) ? 0.f : __expf(e1 - mn);
            float p2 = (e2 <= -1e29f) ? 0.f : __expf(e2 - mn);
            float p3 = (e3 <= -1e29f) ? 0.f : __expf(e3 - mn);
            float rs = p0 + p1 + p2 + p3;
#pragma unroll
            for (int off = 1; off < 16; off <<= 1)
                rs += __shfl_xor_sync(0xFFFFFFFFu, rs, off);
            l[rr] = l[rr] * sc + rs;
            m[rr] = mn;
            acc[rr][0] *= sc; acc[rr][1] *= sc; acc[rr][2] *= sc; acc[rr][3] *= sc;
            *(float4*)&psh[r * PW + tx * 4] = make_float4(p0, p1, p2, p3);
        }
        __syncthreads();

        // ---- P @ H accumulate ----
#pragma unroll 4
        for (int jj = 0; jj < 64; jj++) {
            float4 h4 = *(float4*)&hsh[jj * 64 + tx * 4];
#pragma unroll
            for (int rr = 0; rr < 4; rr++) {
                float pv = psh[(ty * 4 + rr) * PW + jj];
                acc[rr][0] += pv * h4.x;
                acc[rr][1] += pv * h4.y;
                acc[rr][2] += pv * h4.z;
                acc[rr][3] += pv * h4.w;
            }
        }
        __syncthreads();
    }

    // epilogue: normalize and store
#pragma unroll
    for (int rr = 0; rr < 4; rr++) {
        const float inv = (l[rr] > 0.f) ? (1.0f / l[rr]) : 0.f;
        float4 o = make_float4(acc[rr][0] * inv, acc[rr][1] * inv,
                               acc[rr][2] * inv, acc[rr][3] * inv);
        *(float4*)&outp[(size_t)(i0 + ty * 4 + rr) * 64 + tx * 4] = o;
    }
}

// ---------------- final combine ----------------
__global__ void combine_kernel(float* __restrict__ out) {
    const int idx4 = blockIdx.x * blockDim.x + threadIdx.x;
    const int e = idx4 * 4;
    if (e < NGg * DD) {
        const int i = e >> 6;
        const float ga = g_gam_g[i];
        float4 h = *(float4*)&g_gene_h[e];
        float4 A = *(float4*)&g_gg[e];
        float4 B = *(float4*)&g_gc[e];
        float4 o;
        o.x = leaky(h.x + A.x + ga * B.x);
        o.y = leaky(h.y + A.y + ga * B.y);
        o.z = leaky(h.z + A.z + ga * B.z);
        o.w = leaky(h.w + A.w + ga * B.w);
        *(float4*)&out[e] = o;
    } else if (e < (NGg + NCc) * DD) {
        const int e2 = e - NGg * DD;
        const int i = e2 >> 6;
        const float gc_ = g_gam_c[i];
        float4 h = *(float4*)&g_cell_h[e2];
        float4 A = *(float4*)&g_cc[e2];
        float4 B = *(float4*)&g_cg[e2];
        float4 o;
        o.x = leaky(h.x + A.x + gc_ * B.x);
        o.y = leaky(h.y + A.y + gc_ * B.y);
        o.z = leaky(h.z + A.z + gc_ * B.z);
        o.w = leaky(h.w + A.w + gc_ * B.w);
        *(float4*)&out[e] = o;
    }
}

// ---------------- launch ----------------
extern "C" void kernel_launch(void* const* d_in, const int* in_sizes, int n_in,
                              void* d_out, int out_size) {
    const float* gene_x  = (const float*)d_in[0];
    const float* cell_x  = (const float*)d_in[1];
    const float* W_g     = (const float*)d_in[2];
    const float* W_c     = (const float*)d_in[3];
    const float* a_gg    = (const float*)d_in[4];
    const float* a_gc    = (const float*)d_in[5];
    const float* a_cc    = (const float*)d_in[6];
    const float* a_cg    = (const float*)d_in[7];
    const float* Wgate_g = (const float*)d_in[8];
    const float* bgate_g = (const float*)d_in[9];
    const float* Wgate_c = (const float*)d_in[10];
    const float* bgate_c = (const float*)d_in[11];
    const int* gene_adj  = (const int*)d_in[12];
    const int* cell_adj  = (const int*)d_in[13];
    const int* gca       = (const int*)d_in[14];
    float* out = (float*)d_out;

    gemm64_kernel<<<NGg / 16, 256>>>(gene_x, W_g, FGk, 0);
    gemm64_kernel<<<NCc / 16, 256>>>(cell_x, W_c, FCk, 1);
    svec_kernel<<<(NGg + NCc) / 8, 256>>>(a_gg, a_gc, a_cc, a_cg,
                                          Wgate_g, bgate_g, Wgate_c, bgate_c);
    rel_kernel<<<384, 256>>>(gene_adj, cell_adj, gca);
    combine_kernel<<<((NGg + NCc) * DD / 4) / 256, 256>>>(out);
}